// round 1
// baseline (speedup 1.0000x reference)
#include <cuda_runtime.h>
#include <cstdint>

// Problem constants
#define BB   32
#define CC   256
#define HH   56
#define WW   56
#define HWSZ (HH * WW)                 // 3136
#define NPIX (BB * HWSZ)               // 100352
#define NOUT ((size_t)BB * CC * HWSZ)  // 25,690,112
#define KTAP 9
#define NW32 (CC / 32)                 // 8 words per pixel

// -------- scratch (static __device__ arrays: allocation-guard safe) --------
__device__ unsigned       g_xbits[(size_t)NPIX * NW32];          // 3.2 MB
__device__ unsigned       g_wbits[CC * KTAP * NW32];             // 72 KB
__device__ unsigned short g_wpop[CC * KTAP];                     // weight popcount per (co,tap)
__device__ float          g_alpha[CC];
__device__ short          g_S[NOUT];                             // 51.4 MB int16 conv result
__device__ float          g_scale[CC];
__device__ float          g_shift[CC];

// ---------------------------------------------------------------------------
// Kernel 1: pack sign(x) bits, channel-packed per pixel.
// Thread = pixel. For fixed channel c, lanes hit consecutive w -> coalesced.
// ---------------------------------------------------------------------------
__global__ void pack_x_kernel(const float* __restrict__ x) {
    int p = blockIdx.x * blockDim.x + threadIdx.x;   // grid sized exactly
    int b = p / HWSZ;
    int hw = p - b * HWSZ;
    const float* xp = x + (size_t)b * CC * HWSZ + hw;
    unsigned wbuf[NW32];
#pragma unroll
    for (int i = 0; i < NW32; i++) {
        unsigned wv = 0;
#pragma unroll
        for (int j = 0; j < 32; j++) {
            float v = xp[(size_t)(i * 32 + j) * HWSZ];
            wv |= (v > 0.0f ? 1u : 0u) << j;
        }
        wbuf[i] = wv;
    }
#pragma unroll
    for (int i = 0; i < NW32; i++) g_xbits[(size_t)p * NW32 + i] = wbuf[i];
}

// ---------------------------------------------------------------------------
// Kernel 2: weight prep. Block = one output channel, thread = input channel.
// wc = w - mean_ci(w) (per tap), clip, alpha = mean|clip(wc)|, bits = wc>0.
// Deterministic reductions (fixed-order tree, no float atomics).
// ---------------------------------------------------------------------------
__global__ void prep_w_kernel(const float* __restrict__ wt) {
    int co = blockIdx.x;
    int ci = threadIdx.x;
    int lane = ci & 31, warp = ci >> 5;

    __shared__ float part[8][KTAP];
    __shared__ float aprt[8];
    __shared__ float tapmean[KTAP];

    float wv[KTAP];
    const float* wp = wt + ((size_t)co * CC + ci) * KTAP;
#pragma unroll
    for (int t = 0; t < KTAP; t++) wv[t] = wp[t];

#pragma unroll
    for (int t = 0; t < KTAP; t++) {
        float s = wv[t];
#pragma unroll
        for (int o = 16; o > 0; o >>= 1) s += __shfl_down_sync(0xffffffffu, s, o);
        if (lane == 0) part[warp][t] = s;
    }
    __syncthreads();
    if (ci < KTAP) {
        float s = 0.0f;
#pragma unroll
        for (int k = 0; k < 8; k++) s += part[k][ci];
        tapmean[ci] = s * (1.0f / 256.0f);
    }
    __syncthreads();

    float asum = 0.0f;
#pragma unroll
    for (int t = 0; t < KTAP; t++) {
        float wc = wv[t] - tapmean[t];
        wc = fminf(1.0f, fmaxf(-1.0f, wc));
        asum += fabsf(wc);
        unsigned bal = __ballot_sync(0xffffffffu, wc > 0.0f);
        if (lane == 0) g_wbits[(co * KTAP + t) * NW32 + warp] = bal;
    }
#pragma unroll
    for (int o = 16; o > 0; o >>= 1) asum += __shfl_down_sync(0xffffffffu, asum, o);
    if (lane == 0) aprt[warp] = asum;
    __syncthreads();
    if (ci == 0) {
        float s = 0.0f;
#pragma unroll
        for (int k = 0; k < 8; k++) s += aprt[k];
        g_alpha[co] = s * (1.0f / 2304.0f);
    }
    __syncthreads();  // make g_wbits writes visible within block
    if (ci < KTAP) {
        int c = 0;
#pragma unroll
        for (int i = 0; i < NW32; i++) c += __popc(g_wbits[(co * KTAP + ci) * NW32 + i]);
        g_wpop[co * KTAP + ci] = (unsigned short)c;
    }
}

// ---------------------------------------------------------------------------
// Kernel 3: binary conv. Thread = pixel, loop over COB output channels.
// 9x8 x-bit words live in registers; weights broadcast from smem.
// Invalid (padded) taps use x-bits = 0, corrected by precomputed weight popcount.
// S = sum_taps (256 - 2*popc(x^w))  ->  int16 scratch.
// ---------------------------------------------------------------------------
#define COB 128
__global__ void __launch_bounds__(256, 2) conv_bin_kernel() {
    __shared__ unsigned       ws[COB * KTAP * NW32];   // 36 KB
    __shared__ unsigned short wp[COB * KTAP];          // 2.25 KB

    int cobase = blockIdx.y * COB;
    for (int i = threadIdx.x; i < COB * KTAP * NW32; i += 256)
        ws[i] = g_wbits[cobase * KTAP * NW32 + i];
    for (int i = threadIdx.x; i < COB * KTAP; i += 256)
        wp[i] = g_wpop[cobase * KTAP + i];
    __syncthreads();

    int p = blockIdx.x * 256 + threadIdx.x;
    int b = p / HWSZ;
    int hw = p - b * HWSZ;
    int h = hw / WW;
    int w = hw - h * WW;

    unsigned xr[KTAP * NW32];
    unsigned invmask = 0;
#pragma unroll
    for (int dh = -1; dh <= 1; dh++) {
#pragma unroll
        for (int dw = -1; dw <= 1; dw++) {
            int t = (dh + 1) * 3 + (dw + 1);
            int hh = h + dh, ww2 = w + dw;
            bool valid = (hh >= 0) & (hh < HH) & (ww2 >= 0) & (ww2 < WW);
            if (valid) {
                const unsigned* xp = &g_xbits[((size_t)(b * HWSZ + hh * WW + ww2)) * NW32];
#pragma unroll
                for (int i = 0; i < NW32; i++) xr[t * NW32 + i] = xp[i];
            } else {
#pragma unroll
                for (int i = 0; i < NW32; i++) xr[t * NW32 + i] = 0u;
                invmask |= 1u << t;
            }
        }
    }

    short* Sout = &g_S[((size_t)b * CC + cobase) * HWSZ + hw];
    for (int c = 0; c < COB; c++) {
        int psum = 0;
        const unsigned* wrow = &ws[c * KTAP * NW32];
#pragma unroll
        for (int j = 0; j < KTAP * NW32; j++) psum += __popc(xr[j] ^ wrow[j]);
        int S = CC * KTAP - 2 * psum;   // 2304 - 2*sum(popc)
        if (invmask) {
            unsigned m = invmask;
            while (m) {
                int t = __ffs(m) - 1;
                m &= m - 1;
                S -= CC - 2 * (int)wp[c * KTAP + t];  // remove phantom padded-tap term
            }
        }
        Sout[(size_t)c * HWSZ] = (short)S;
    }
}

// ---------------------------------------------------------------------------
// Kernel 4: per-channel BN stats from exact integer sums -> threshold affine.
// y = alpha*S + bias ; mu_y = alpha*meanS + bias ; var_y = alpha^2*varS
// out = 1 iff gamma*(y-mu)*rsqrt(var+eps) + beta > 0
//     = 1 iff scale*S + shift > 0
// ---------------------------------------------------------------------------
__global__ void bn_stats_kernel(const float* __restrict__ bias,
                                const float* __restrict__ gamma,
                                const float* __restrict__ beta) {
    int co = blockIdx.x;
    long long s = 0, sq = 0;
    for (int b = 0; b < BB; b++) {
        const short* Sp = &g_S[((size_t)(b * CC + co)) * HWSZ];
        for (int i = threadIdx.x; i < HWSZ; i += blockDim.x) {
            int v = Sp[i];
            s += v;
            sq += (long long)(v * v);
        }
    }
    // lane reduce (integer: order-independent, exact)
#pragma unroll
    for (int o = 16; o > 0; o >>= 1) {
        s  += __shfl_down_sync(0xffffffffu, s, o);
        sq += __shfl_down_sync(0xffffffffu, sq, o);
    }
    __shared__ unsigned long long ss, ssq;
    if (threadIdx.x == 0) { ss = 0ull; ssq = 0ull; }
    __syncthreads();
    if ((threadIdx.x & 31) == 0) {
        atomicAdd(&ss, (unsigned long long)s);
        atomicAdd(&ssq, (unsigned long long)sq);
    }
    __syncthreads();
    if (threadIdx.x == 0) {
        double n = (double)(BB * HWSZ);
        double mean = (double)(long long)ss / n;
        double var = (double)(long long)ssq / n - mean * mean;
        double a = (double)g_alpha[co];
        double vy = a * a * var;
        double rs = 1.0 / sqrt(vy + 1e-5);
        double g = (double)gamma[co];
        g_scale[co] = (float)(g * rs * a);
        g_shift[co] = (float)((double)beta[co] - g * rs * a * mean);
    }
}

// ---------------------------------------------------------------------------
// Kernel 5: elementwise threshold -> {0,1} fp32, vectorized x4.
// ---------------------------------------------------------------------------
__global__ void finalize_kernel(float* __restrict__ out) {
    size_t i4 = (size_t)blockIdx.x * blockDim.x + threadIdx.x;
    size_t i = i4 * 4;
    int co = (int)((i / HWSZ) % CC);   // HWSZ % 4 == 0 -> same channel for all 4
    float sc = g_scale[co], sh = g_shift[co];
    short4 s = *(const short4*)&g_S[i];
    float4 o;
    o.x = (sc * (float)s.x + sh > 0.0f) ? 1.0f : 0.0f;
    o.y = (sc * (float)s.y + sh > 0.0f) ? 1.0f : 0.0f;
    o.z = (sc * (float)s.z + sh > 0.0f) ? 1.0f : 0.0f;
    o.w = (sc * (float)s.w + sh > 0.0f) ? 1.0f : 0.0f;
    *(float4*)&out[i] = o;
}

// ---------------------------------------------------------------------------
extern "C" void kernel_launch(void* const* d_in, const int* in_sizes, int n_in,
                              void* d_out, int out_size) {
    const float* x      = (const float*)d_in[0];
    const float* weight = (const float*)d_in[1];
    const float* bias   = (const float*)d_in[2];
    const float* gamma  = (const float*)d_in[3];
    const float* beta   = (const float*)d_in[4];
    float* out = (float*)d_out;

    pack_x_kernel<<<NPIX / 256, 256>>>(x);            // 392 blocks
    prep_w_kernel<<<CC, 256>>>(weight);               // 256 blocks
    conv_bin_kernel<<<dim3(NPIX / 256, CC / COB), 256>>>();  // 392 x 2
    bn_stats_kernel<<<CC, 256>>>(bias, gamma, beta);
    finalize_kernel<<<(unsigned)(NOUT / 4 / 256), 256>>>(out);  // 25088 blocks
}

// round 2
// speedup vs baseline: 2.0414x; 2.0414x over previous
#include <cuda_runtime.h>
#include <cstdint>

// Problem constants
#define BB   32
#define CC   256
#define HH   56
#define WW   56
#define HWSZ (HH * WW)                 // 3136
#define NPIX (BB * HWSZ)               // 100352
#define NOUT ((size_t)BB * CC * HWSZ)  // 25,690,112
#define KTAP 9
#define NW32 (CC / 32)                 // 8 words per pixel

// -------- scratch (static __device__ arrays: allocation-guard safe) --------
__device__ unsigned           g_xbits[(size_t)NPIX * NW32];      // 3.2 MB
__device__ unsigned           g_wbits[CC * KTAP * NW32];         // 72 KB
__device__ unsigned short     g_wpop[CC * KTAP];
__device__ int                g_corr[9 * CC];                    // boundary-class correction
__device__ float              g_alpha[CC];
__device__ short              g_S[NOUT];                         // 51.4 MB int16 conv result
__device__ int                g_chsum[CC];
__device__ unsigned long long g_chsq[CC];
__device__ float              g_scale[CC];
__device__ float              g_shift[CC];

// ---------------------------------------------------------------------------
// Kernel 1: pack sign(x) bits, channel-packed per pixel.
// ---------------------------------------------------------------------------
__global__ void pack_x_kernel(const float* __restrict__ x) {
    int p = blockIdx.x * blockDim.x + threadIdx.x;
    int b = p / HWSZ;
    int hw = p - b * HWSZ;
    const float* xp = x + (size_t)b * CC * HWSZ + hw;
    unsigned wbuf[NW32];
#pragma unroll
    for (int i = 0; i < NW32; i++) {
        unsigned wv = 0;
#pragma unroll
        for (int j = 0; j < 32; j++) {
            float v = xp[(size_t)(i * 32 + j) * HWSZ];
            wv |= (v > 0.0f ? 1u : 0u) << j;
        }
        wbuf[i] = wv;
    }
#pragma unroll
    for (int i = 0; i < NW32; i++) g_xbits[(size_t)p * NW32 + i] = wbuf[i];
}

// ---------------------------------------------------------------------------
// Kernel 2: weight prep + boundary-correction table.
// Block = output channel, thread = input channel.
// ---------------------------------------------------------------------------
__global__ void prep_w_kernel(const float* __restrict__ wt) {
    int co = blockIdx.x;
    int ci = threadIdx.x;
    int lane = ci & 31, warp = ci >> 5;

    __shared__ float part[8][KTAP];
    __shared__ float aprt[8];
    __shared__ float tapmean[KTAP];

    float wv[KTAP];
    const float* wp = wt + ((size_t)co * CC + ci) * KTAP;
#pragma unroll
    for (int t = 0; t < KTAP; t++) wv[t] = wp[t];

#pragma unroll
    for (int t = 0; t < KTAP; t++) {
        float s = wv[t];
#pragma unroll
        for (int o = 16; o > 0; o >>= 1) s += __shfl_down_sync(0xffffffffu, s, o);
        if (lane == 0) part[warp][t] = s;
    }
    __syncthreads();
    if (ci < KTAP) {
        float s = 0.0f;
#pragma unroll
        for (int k = 0; k < 8; k++) s += part[k][ci];
        tapmean[ci] = s * (1.0f / 256.0f);
    }
    __syncthreads();

    float asum = 0.0f;
#pragma unroll
    for (int t = 0; t < KTAP; t++) {
        float wc = wv[t] - tapmean[t];
        wc = fminf(1.0f, fmaxf(-1.0f, wc));
        asum += fabsf(wc);
        unsigned bal = __ballot_sync(0xffffffffu, wc > 0.0f);
        if (lane == 0) g_wbits[(co * KTAP + t) * NW32 + warp] = bal;
    }
#pragma unroll
    for (int o = 16; o > 0; o >>= 1) asum += __shfl_down_sync(0xffffffffu, asum, o);
    if (lane == 0) aprt[warp] = asum;
    __syncthreads();
    if (ci == 0) {
        float s = 0.0f;
#pragma unroll
        for (int k = 0; k < 8; k++) s += aprt[k];
        g_alpha[co] = s * (1.0f / 2304.0f);
    }
    __syncthreads();

    __shared__ int wpop_s[KTAP];
    if (ci < KTAP) {
        int c = 0;
#pragma unroll
        for (int i = 0; i < NW32; i++) c += __popc(g_wbits[(co * KTAP + ci) * NW32 + i]);
        g_wpop[co * KTAP + ci] = (unsigned short)c;
        wpop_s[ci] = c;
    }
    __syncthreads();
    // Boundary-class corrections: class = hcls*3 + wcls.
    // For every tap that falls outside the image, x-bits were 0, so popc(0^w)=wpop
    // contributed (256 - 2*wpop) erroneously; precompute the sum to subtract.
    if (ci < 9) {
        int hcls = ci / 3, wcls = ci % 3;
        int corr = 0;
#pragma unroll
        for (int t = 0; t < KTAP; t++) {
            int dh = t / 3 - 1, dw = t % 3 - 1;
            bool inv = (hcls == 0 && dh < 0) || (hcls == 2 && dh > 0) ||
                       (wcls == 0 && dw < 0) || (wcls == 2 && dw > 0);
            if (inv) corr += CC - 2 * wpop_s[t];
        }
        g_corr[ci * CC + co] = corr;
    }
}

// ---------------------------------------------------------------------------
// Kernel 3: binary conv. Thread = pixel, loop over all 256 output channels.
// Weights staged once per block as uint4 (18 LDS.128 per channel).
// Padding handled by precomputed per-class correction (no divergent loop).
// ---------------------------------------------------------------------------
__global__ void __launch_bounds__(256, 2) conv_bin_kernel() {
    __shared__ uint4 ws[CC * (KTAP * NW32 / 4)];   // 256 * 18 uint4 = 36 KB
    __shared__ int   corr_s[9 * CC];               // 9 KB

    {
        const uint4* src = (const uint4*)g_wbits;
        for (int i = threadIdx.x; i < CC * 18; i += 256) ws[i] = src[i];
        for (int i = threadIdx.x; i < 9 * CC; i += 256) corr_s[i] = g_corr[i];
    }
    __syncthreads();

    int p = blockIdx.x * 256 + threadIdx.x;
    int b = p / HWSZ;
    int hw = p - b * HWSZ;
    int h = hw / WW;
    int w = hw - h * WW;
    int hcls = (h == 0) ? 0 : ((h == HH - 1) ? 2 : 1);
    int wcls = (w == 0) ? 0 : ((w == WW - 1) ? 2 : 1);
    const int* corr_row = &corr_s[(hcls * 3 + wcls) * CC];

    unsigned xr[KTAP * NW32];
#pragma unroll
    for (int dh = -1; dh <= 1; dh++) {
#pragma unroll
        for (int dw = -1; dw <= 1; dw++) {
            int t = (dh + 1) * 3 + (dw + 1);
            int hh = h + dh, ww2 = w + dw;
            bool valid = (hh >= 0) & (hh < HH) & (ww2 >= 0) & (ww2 < WW);
            if (valid) {
                const unsigned* xp = &g_xbits[((size_t)(b * HWSZ + hh * WW + ww2)) * NW32];
#pragma unroll
                for (int i = 0; i < NW32; i++) xr[t * NW32 + i] = xp[i];
            } else {
#pragma unroll
                for (int i = 0; i < NW32; i++) xr[t * NW32 + i] = 0u;
            }
        }
    }

    short* Sout = &g_S[((size_t)b * CC) * HWSZ + hw];
#pragma unroll 2
    for (int c = 0; c < CC; c++) {
        const uint4* wrow = &ws[c * 18];
        int psum = 0;
#pragma unroll
        for (int j = 0; j < 18; j++) {
            uint4 wv = wrow[j];
            psum += __popc(xr[4 * j + 0] ^ wv.x);
            psum += __popc(xr[4 * j + 1] ^ wv.y);
            psum += __popc(xr[4 * j + 2] ^ wv.z);
            psum += __popc(xr[4 * j + 3] ^ wv.w);
        }
        int S = CC * KTAP - 2 * psum - corr_row[c];
        Sout[(size_t)c * HWSZ] = (short)S;
    }
}

// ---------------------------------------------------------------------------
// Kernel 4a: zero the per-channel stat accumulators (graph-replay safe).
// ---------------------------------------------------------------------------
__global__ void zero_stats_kernel() {
    int c = threadIdx.x;
    g_chsum[c] = 0;
    g_chsq[c] = 0ull;
}

// ---------------------------------------------------------------------------
// Kernel 4b: fast per-channel stats. Block = one (b,c) slab of 3136 shorts.
// uint4 loads, exact integer reduction, integer atomics (deterministic).
// ---------------------------------------------------------------------------
__global__ void stats_kernel() {
    int bc = blockIdx.x;               // b*CC + c
    int c  = bc & (CC - 1);
    const uint4* p4 = (const uint4*)&g_S[(size_t)bc * HWSZ];   // 392 uint4 per slab
    int tid = threadIdx.x;             // 128 threads

    int s = 0;
    unsigned sq = 0;
    for (int i = tid; i < HWSZ / 8; i += 128) {
        uint4 v = p4[i];
#pragma unroll
        for (int k = 0; k < 4; k++) {
            unsigned u = (&v.x)[k];
            int lo = (short)(u & 0xffffu);
            int hi = (short)(u >> 16);
            s += lo + hi;
            sq += (unsigned)(lo * lo) + (unsigned)(hi * hi);
        }
    }
#pragma unroll
    for (int o = 16; o > 0; o >>= 1) {
        s  += __shfl_down_sync(0xffffffffu, s, o);
        sq += __shfl_down_sync(0xffffffffu, sq, o);
    }
    __shared__ int sh_s[4];
    __shared__ unsigned sh_q[4];
    int lane = tid & 31, warp = tid >> 5;
    if (lane == 0) { sh_s[warp] = s; sh_q[warp] = sq; }
    __syncthreads();
    if (tid == 0) {
        int ts = sh_s[0] + sh_s[1] + sh_s[2] + sh_s[3];
        unsigned long long tq = (unsigned long long)sh_q[0] + sh_q[1] + sh_q[2] + sh_q[3];
        atomicAdd(&g_chsum[c], ts);
        atomicAdd(&g_chsq[c], tq);
    }
}

// ---------------------------------------------------------------------------
// Kernel 4c: fold stats into the per-channel affine threshold.
// out = 1 iff gamma*(alpha*S + bias - mu)*rsqrt(var+eps) + beta > 0
//     = 1 iff scale*S + shift > 0
// ---------------------------------------------------------------------------
__global__ void params_kernel(const float* __restrict__ bias,
                              const float* __restrict__ gamma,
                              const float* __restrict__ beta) {
    int co = threadIdx.x;
    double n = (double)(BB * HWSZ);
    double mean = (double)g_chsum[co] / n;
    double var = (double)(long long)g_chsq[co] / n - mean * mean;
    double a = (double)g_alpha[co];
    double vy = a * a * var;
    double rs = 1.0 / sqrt(vy + 1e-5);
    double g = (double)gamma[co];
    g_scale[co] = (float)(g * rs * a);
    g_shift[co] = (float)((double)beta[co] - g * rs * a * mean);
}

// ---------------------------------------------------------------------------
// Kernel 5: elementwise threshold -> {0,1} fp32, vectorized x4.
// ---------------------------------------------------------------------------
__global__ void finalize_kernel(float* __restrict__ out) {
    size_t i4 = (size_t)blockIdx.x * blockDim.x + threadIdx.x;
    size_t i = i4 * 4;
    int co = (int)((i / HWSZ) % CC);   // HWSZ % 4 == 0 -> same channel for all 4
    float sc = g_scale[co], sh = g_shift[co];
    short4 s = *(const short4*)&g_S[i];
    float4 o;
    o.x = (sc * (float)s.x + sh > 0.0f) ? 1.0f : 0.0f;
    o.y = (sc * (float)s.y + sh > 0.0f) ? 1.0f : 0.0f;
    o.z = (sc * (float)s.z + sh > 0.0f) ? 1.0f : 0.0f;
    o.w = (sc * (float)s.w + sh > 0.0f) ? 1.0f : 0.0f;
    *(float4*)&out[i] = o;
}

// ---------------------------------------------------------------------------
extern "C" void kernel_launch(void* const* d_in, const int* in_sizes, int n_in,
                              void* d_out, int out_size) {
    const float* x      = (const float*)d_in[0];
    const float* weight = (const float*)d_in[1];
    const float* bias   = (const float*)d_in[2];
    const float* gamma  = (const float*)d_in[3];
    const float* beta   = (const float*)d_in[4];
    float* out = (float*)d_out;

    pack_x_kernel<<<NPIX / 256, 256>>>(x);            // 392 blocks
    prep_w_kernel<<<CC, 256>>>(weight);               // 256 blocks
    zero_stats_kernel<<<1, CC>>>();
    conv_bin_kernel<<<NPIX / 256, 256>>>();           // 392 blocks
    stats_kernel<<<BB * CC, 128>>>();                 // 8192 blocks
    params_kernel<<<1, CC>>>(bias, gamma, beta);
    finalize_kernel<<<(unsigned)(NOUT / 4 / 256), 256>>>(out);
}